// round 8
// baseline (speedup 1.0000x reference)
#include <cuda_runtime.h>
#include <cuda_fp16.h>
#include <cstdint>

// ---------------------------------------------------------------------------
// CFConvAngular: all-MMA, 2-phase pipelined tiles. 256 threads, 2 CTAs/SM.
// Phase A: GEMM1 (H1^T = ssp(Wf1^T @ R^T + bf1)) + z-build (z = yj*yk*m)
// Phase B: stage next r-tile/indices + GEMM2 (D^T = Wf2^T @ H1^T) + epilogue
// out = ssp(acc @ Wout + bout)
// ---------------------------------------------------------------------------

#define B_DIM 2
#define A_DIM 512
#define T_DIM 512
#define F_DIM 128
#define R_DIM 25
#define TT    128
#define NTILES (T_DIM / TT)     // 4
#define NT    256               // 8 warps

__device__ float g_y[B_DIM * A_DIM * F_DIM];

__device__ __forceinline__ uint32_t smem_u32(const void* p) {
    uint32_t a;
    asm("{ .reg .u64 t; cvta.to.shared.u64 t, %1; cvt.u32.u64 %0, t; }" : "=r"(a) : "l"(p));
    return a;
}

__device__ __forceinline__ float sspf(float v) {
    float e = __expf(-fabsf(v));
    return fmaxf(v, 0.0f) + __logf(1.0f + e) - 0.69314718055994530942f;
}

__device__ __forceinline__ void mma16816(float& c0, float& c1, float& c2, float& c3,
                                         uint32_t a0, uint32_t a1, uint32_t a2, uint32_t a3,
                                         uint32_t b0, uint32_t b1) {
    asm volatile("mma.sync.aligned.m16n8k16.row.col.f32.f16.f16.f32 "
                 "{%0,%1,%2,%3}, {%4,%5,%6,%7}, {%8,%9}, {%0,%1,%2,%3};"
                 : "+f"(c0), "+f"(c1), "+f"(c2), "+f"(c3)
                 : "r"(a0), "r"(a1), "r"(a2), "r"(a3), "r"(b0), "r"(b1));
}

__device__ __forceinline__ void ldsm_x4(uint32_t& r0, uint32_t& r1,
                                        uint32_t& r2, uint32_t& r3, uint32_t addr) {
    asm volatile("ldmatrix.sync.aligned.m8n8.x4.shared.b16 {%0,%1,%2,%3}, [%4];"
                 : "=r"(r0), "=r"(r1), "=r"(r2), "=r"(r3) : "r"(addr));
}
__device__ __forceinline__ void ldsm_x4_t(uint32_t& r0, uint32_t& r1,
                                          uint32_t& r2, uint32_t& r3, uint32_t addr) {
    asm volatile("ldmatrix.sync.aligned.m8n8.x4.trans.shared.b16 {%0,%1,%2,%3}, [%4];"
                 : "=r"(r0), "=r"(r1), "=r"(r2), "=r"(r3) : "r"(addr));
}

__device__ __forceinline__ uint32_t h2u(float a, float b) {
    __half2 h = __floats2half2_rn(a, b);
    return *(uint32_t*)&h;
}

// ------------------------- kernel 1: y = x @ Win ---------------------------
__global__ void __launch_bounds__(F_DIM) in2f_kernel(
    const float* __restrict__ x, const float* __restrict__ Win)
{
    __shared__ float sx[F_DIM];
    const int tid = threadIdx.x;
    const int blk = blockIdx.x;
    sx[tid] = x[blk * F_DIM + tid];
    __syncthreads();
    float s0 = 0.f, s1 = 0.f, s2 = 0.f, s3 = 0.f;
#pragma unroll
    for (int i = 0; i < F_DIM; i += 4) {
        s0 = fmaf(sx[i + 0], Win[(i + 0) * F_DIM + tid], s0);
        s1 = fmaf(sx[i + 1], Win[(i + 1) * F_DIM + tid], s1);
        s2 = fmaf(sx[i + 2], Win[(i + 2) * F_DIM + tid], s2);
        s3 = fmaf(sx[i + 3], Win[(i + 3) * F_DIM + tid], s3);
    }
    g_y[blk * F_DIM + tid] = (s0 + s1) + (s2 + s3);
}

// ------------------------- main fused kernel -------------------------------
#define H1T_STRIDE_B 272                 // 128 k-rows x (128 t + pad) fp16
#define RH_STRIDE_B  80                  // 128 t-rows x (32 r + pad) fp16
#define Z_STRIDE     132                 // fp32 words/row; 2*132 mod 32 = 8 ->
                                         // epilogue banks 8*tig+g: conflict-free
#define OFF_H1T  0                       // 34816
#define OFF_Z    34816                   // 128*132*4 = 67584 -> 102400
#define OFF_RH   102400                  // 128*80 = 10240 -> 112640 (own region)
#define OFF_J    112640                  // 128 int
#define OFF_K    113152                  // 128 int
#define OFF_M    113664                  // 128 f32
#define OFF_ACC  114176                  // 128 f32
#define SMEM_BYTES 114688                // 112 KB -> 2 CTAs/SM (224 <= 228KB)

__global__ void __launch_bounds__(NT, 2) cfconv_kernel(
    const float* __restrict__ r_ij, const float* __restrict__ mask,
    const float* __restrict__ Wf1, const float* __restrict__ bf1,
    const float* __restrict__ Wf2, const float* __restrict__ bf2,
    const float* __restrict__ Wout, const float* __restrict__ bout,
    const int* __restrict__ nj, const int* __restrict__ nk,
    float* __restrict__ out)
{
    extern __shared__ char smem[];
    const int tid  = threadIdx.x;
    const int lane = tid & 31;
    const int wid  = tid >> 5;
    const int g    = lane >> 2;
    const int tig  = lane & 3;
    const int blk  = blockIdx.x;
    const int b    = blk >> 9;

    int*   sJ   = (int*)(smem + OFF_J);
    int*   sK   = (int*)(smem + OFF_K);
    float* sM   = (float*)(smem + OFF_M);
    float* sAcc = (float*)(smem + OFF_ACC);
    float* sZ   = (float*)(smem + OFF_Z);
    const uint32_t sH1Tu = smem_u32(smem + OFF_H1T);
    const uint32_t sRHu  = smem_u32(smem + OFF_RH);
    __half* sRh = (__half*)(smem + OFF_RH);

    const int rw   = wid * 16;
    const int m_lo = rw + g;
    const int m_hi = rw + g + 8;

    // ---- GEMM1 A-frags: Wf1^T[kc][r], K=32 (r>=25 zero) ----
    uint32_t aW[2][4];
#pragma unroll
    for (int s = 0; s < 2; s++) {
        const int r0 = s * 16 + 2 * tig;
#pragma unroll
        for (int q = 0; q < 4; q++) {
            const int rr = r0 + (q >> 1) * 8;
            const int cc = (q & 1) ? m_hi : m_lo;
            const float v0 = (rr     < R_DIM) ? Wf1[rr * F_DIM + cc]       : 0.f;
            const float v1 = (rr + 1 < R_DIM) ? Wf1[(rr + 1) * F_DIM + cc] : 0.f;
            aW[s][q] = h2u(v0, v1);
        }
    }

    // ---- GEMM2 A-frags: Wf2^T[f][k] ----
    uint32_t aA[8][4];
#pragma unroll
    for (int ks = 0; ks < 8; ks++) {
        const int k0 = ks * 16 + tig * 2;
        aA[ks][0] = h2u(Wf2[k0 * F_DIM + m_lo],       Wf2[(k0 + 1) * F_DIM + m_lo]);
        aA[ks][1] = h2u(Wf2[k0 * F_DIM + m_hi],       Wf2[(k0 + 1) * F_DIM + m_hi]);
        aA[ks][2] = h2u(Wf2[(k0 + 8) * F_DIM + m_lo], Wf2[(k0 + 9) * F_DIM + m_lo]);
        aA[ks][3] = h2u(Wf2[(k0 + 8) * F_DIM + m_hi], Wf2[(k0 + 9) * F_DIM + m_hi]);
    }
    const float bf1_lo = bf1[m_lo], bf1_hi = bf1[m_hi];
    const float bf2_lo = bf2[m_lo], bf2_hi = bf2[m_hi];

    const uint32_t rh_off  = (uint32_t)((lane & 7) * RH_STRIDE_B + (lane >> 3) * 16);
    const uint32_t h1t_off = (uint32_t)(((lane >> 3) * 8 + (lane & 7)) * H1T_STRIDE_B);

    const long   rbase = (long)blk * T_DIM * R_DIM;
    const int    tbase = blk * T_DIM;
    const float* ybase = g_y + (long)b * A_DIM * F_DIM;

    const int zb_tsub = wid;              // z-build: warp-uniform t offset
    const int zb_f4   = lane * 4;

    float acc_lo = 0.f, acc_hi = 0.f;

    // ---- stage tile 0 ----
    {
        const float* rsrc = r_ij + rbase;
        for (int e = tid; e < TT * 32; e += NT) {
            const int t = e >> 5, r = e & 31;
            const float v = (r < R_DIM) ? rsrc[t * R_DIM + r] : 0.f;
            sRh[t * (RH_STRIDE_B / 2) + r] = __float2half_rn(v);
        }
        if (tid < TT) {
            sJ[tid] = nj[tbase + tid];
            sK[tid] = nk[tbase + tid];
            sM[tid] = mask[tbase + tid];
        }
    }
    __syncthreads();

    for (int tile = 0; tile < NTILES; ++tile) {
        // ================= Phase A: GEMM1 + z-build =================
#pragma unroll 4
        for (int nb = 0; nb < 16; nb++) {
            uint32_t q0, q1, q2, q3;
            ldsm_x4(q0, q1, q2, q3, sRHu + (uint32_t)(nb * 8 * RH_STRIDE_B) + rh_off);
            float c0 = 0.f, c1 = 0.f, c2 = 0.f, c3 = 0.f;
            mma16816(c0, c1, c2, c3, aW[0][0], aW[0][1], aW[0][2], aW[0][3], q0, q1);
            mma16816(c0, c1, c2, c3, aW[1][0], aW[1][1], aW[1][2], aW[1][3], q2, q3);
            const int t0 = nb * 8 + 2 * tig;
            const uint32_t u_lo = h2u(sspf(c0 + bf1_lo), sspf(c1 + bf1_lo));
            const uint32_t u_hi = h2u(sspf(c2 + bf1_hi), sspf(c3 + bf1_hi));
            *(uint32_t*)(smem + OFF_H1T + m_lo * H1T_STRIDE_B + t0 * 2) = u_lo;
            *(uint32_t*)(smem + OFF_H1T + m_hi * H1T_STRIDE_B + t0 * 2) = u_hi;
        }
        // z-build (independent of GEMM1, same phase)
#pragma unroll
        for (int i = 0; i < 16; i++) {
            const int t  = i * 8 + zb_tsub;
            const int jj = sJ[t];
            const int kk = sK[t];
            const float m = sM[t];
            const float4 yj = *(const float4*)(ybase + jj * F_DIM + zb_f4);
            const float4 yk = *(const float4*)(ybase + kk * F_DIM + zb_f4);
            float4 z;
            z.x = yj.x * yk.x * m;
            z.y = yj.y * yk.y * m;
            z.z = yj.z * yk.z * m;
            z.w = yj.w * yk.w * m;
            *(float4*)(sZ + t * Z_STRIDE + zb_f4) = z;
        }
        __syncthreads();   // H1T + Z ready; RH/J/K/M free

        // ====== Phase B: stage next tile + GEMM2 + epilogue ======
        if (tile + 1 < NTILES) {
            const float* rsrc = r_ij + rbase + (long)(tile + 1) * TT * R_DIM;
            for (int e = tid; e < TT * 32; e += NT) {
                const int t = e >> 5, r = e & 31;
                const float v = (r < R_DIM) ? rsrc[t * R_DIM + r] : 0.f;
                sRh[t * (RH_STRIDE_B / 2) + r] = __float2half_rn(v);
            }
            const int toff = tbase + (tile + 1) * TT;
            if (tid < TT) {
                sJ[tid] = nj[toff + tid];
                sK[tid] = nk[toff + tid];
                sM[tid] = mask[toff + tid];
            }
        }

#pragma unroll 2
        for (int nb = 0; nb < 16; nb++) {
            float c0 = 0.f, c1 = 0.f, c2 = 0.f, c3 = 0.f;
#pragma unroll
            for (int kq = 0; kq < 4; kq++) {
                uint32_t q0, q1, q2, q3;
                ldsm_x4_t(q0, q1, q2, q3,
                          sH1Tu + (uint32_t)(kq * 32 * H1T_STRIDE_B) + h1t_off
                                + (uint32_t)(nb * 16));
                mma16816(c0, c1, c2, c3,
                         aA[2 * kq][0], aA[2 * kq][1], aA[2 * kq][2], aA[2 * kq][3],
                         q0, q1);
                mma16816(c0, c1, c2, c3,
                         aA[2 * kq + 1][0], aA[2 * kq + 1][1], aA[2 * kq + 1][2], aA[2 * kq + 1][3],
                         q2, q3);
            }
            const int t_a = nb * 8 + tig * 2;
            const int t_b = t_a + 1;
            const float za_lo = sZ[t_a * Z_STRIDE + m_lo];
            const float zb_lo = sZ[t_b * Z_STRIDE + m_lo];
            const float za_hi = sZ[t_a * Z_STRIDE + m_hi];
            const float zb_hi = sZ[t_b * Z_STRIDE + m_hi];
            acc_lo = fmaf(c0 + bf2_lo, za_lo, acc_lo);
            acc_lo = fmaf(c1 + bf2_lo, zb_lo, acc_lo);
            acc_hi = fmaf(c2 + bf2_hi, za_hi, acc_hi);
            acc_hi = fmaf(c3 + bf2_hi, zb_hi, acc_hi);
        }
        __syncthreads();   // next tile's RH/J/K/M staged; H1T/Z free
    }

    // ---- quad reduction and publish ----
    acc_lo += __shfl_xor_sync(0xFFFFFFFF, acc_lo, 1);
    acc_lo += __shfl_xor_sync(0xFFFFFFFF, acc_lo, 2);
    acc_hi += __shfl_xor_sync(0xFFFFFFFF, acc_hi, 1);
    acc_hi += __shfl_xor_sync(0xFFFFFFFF, acc_hi, 2);
    if (tig == 0) {
        sAcc[m_lo] = acc_lo;
        sAcc[m_hi] = acc_hi;
    }
    __syncthreads();

    // ---- f2out ----
    if (tid < F_DIM) {
        float s0 = 0.f, s1 = 0.f, s2 = 0.f, s3 = 0.f;
#pragma unroll
        for (int f = 0; f < F_DIM; f += 4) {
            s0 = fmaf(sAcc[f + 0], Wout[(f + 0) * F_DIM + tid], s0);
            s1 = fmaf(sAcc[f + 1], Wout[(f + 1) * F_DIM + tid], s1);
            s2 = fmaf(sAcc[f + 2], Wout[(f + 2) * F_DIM + tid], s2);
            s3 = fmaf(sAcc[f + 3], Wout[(f + 3) * F_DIM + tid], s3);
        }
        out[blk * F_DIM + tid] = sspf((s0 + s1) + (s2 + s3) + bout[tid]);
    }
}

// ------------------------------- launcher ----------------------------------
extern "C" void kernel_launch(void* const* d_in, const int* in_sizes, int n_in,
                              void* d_out, int out_size)
{
    const float* x    = (const float*)d_in[0];
    const float* r_ij = (const float*)d_in[1];
    const float* mask = (const float*)d_in[2];
    const float* Wf1  = (const float*)d_in[3];
    const float* bf1  = (const float*)d_in[4];
    const float* Wf2  = (const float*)d_in[5];
    const float* bf2  = (const float*)d_in[6];
    const float* Win  = (const float*)d_in[7];
    const float* Wout = (const float*)d_in[8];
    const float* bout = (const float*)d_in[9];
    const int*   nj   = (const int*)d_in[10];
    const int*   nk   = (const int*)d_in[11];
    float* out = (float*)d_out;

    cudaFuncSetAttribute(cfconv_kernel,
                         cudaFuncAttributeMaxDynamicSharedMemorySize, SMEM_BYTES);

    in2f_kernel<<<B_DIM * A_DIM, F_DIM>>>(x, Win);
    cfconv_kernel<<<B_DIM * A_DIM, NT, SMEM_BYTES>>>(
        r_ij, mask, Wf1, bf1, Wf2, bf2, Wout, bout, nj, nk, out);
}